// round 2
// baseline (speedup 1.0000x reference)
#include <cuda_runtime.h>
#include <math.h>

// Problem constants
#define T_    512
#define B_    64
#define H_    1024
#define C_    32000
#define SIXH  6144
#define M_    (T_*B_)        // 32768 rows of xin
#define YSIZE (B_*C_)        // 2,048,000 floats of y
#define GRID_G 128           // persistent kernel CTAs (<=148 SMs => co-resident)

// -------- scratch (no cudaMalloc allowed) --------
__device__ float    g_xin[M_*H_];       // 134 MB: xin[t*64+b][n]
__device__ float    g_h[B_*H_];         // current hidden state
__device__ float    g_part[8*B_*H_];    // K-split partial sums: part[ks][b][n]
__device__ unsigned g_count = 0;        // barrier arrival counter (self-resets)
__device__ unsigned g_gen   = 0;        // barrier generation (monotonic)

// -------- software grid barrier (all GRID_G CTAs co-resident) --------
__device__ __forceinline__ void grid_sync() {
    __syncthreads();
    if (threadIdx.x == 0) {
        __threadfence();  // release: make this CTA's writes visible
        unsigned gen = *((volatile unsigned*)&g_gen);
        if (atomicAdd(&g_count, 1u) == GRID_G - 1) {
            atomicExch(&g_count, 0u);   // reset for next barrier (and next replay)
            __threadfence();
            *((volatile unsigned*)&g_gen) = gen + 1u;
        } else {
            while (*((volatile unsigned*)&g_gen) == gen) { }
        }
        __threadfence();  // acquire (also invalidates L1)
    }
    __syncthreads();
}

// ================= Kernel 1: xin = emb[x] @ Wx + b =================
// M=32768, N=1024, K=1024.  64x64 tile, 256 threads, 4x4 per thread, K-tile 16.
__global__ void xin_kernel(const int* __restrict__ x, const float* __restrict__ emb,
                           const float* __restrict__ w1, const float* __restrict__ b1) {
    __shared__ __align__(16) float As[64*16];   // As[row][kk]
    __shared__ __align__(16) float Bs[16*64];   // Bs[kk][n]
    __shared__ int rows[64];
    const int tid = threadIdx.x;
    const int n0 = blockIdx.x * 64;
    const int r0 = blockIdx.y * 64;
    const int tx = tid & 15, ty = tid >> 4;

    if (tid < 64) rows[tid] = x[r0 + tid];
    __syncthreads();

    float acc[4][4] = {};
    for (int k0 = 0; k0 < H_; k0 += 16) {
        #pragma unroll
        for (int j = 0; j < 4; j++) {
            int f = tid + j * 256;
            int row = f >> 4, kk = f & 15;
            As[row * 16 + kk] = emb[rows[row] * H_ + k0 + kk];
            int bkk = f >> 6, bn = f & 63;
            Bs[bkk * 64 + bn] = w1[(k0 + bkk) * SIXH + n0 + bn];
        }
        __syncthreads();
        #pragma unroll
        for (int kk = 0; kk < 16; kk++) {
            float a0 = As[(ty*4+0)*16 + kk];
            float a1 = As[(ty*4+1)*16 + kk];
            float a2 = As[(ty*4+2)*16 + kk];
            float a3 = As[(ty*4+3)*16 + kk];
            float4 bv = *(const float4*)&Bs[kk*64 + tx*4];
            acc[0][0] += a0*bv.x; acc[0][1] += a0*bv.y; acc[0][2] += a0*bv.z; acc[0][3] += a0*bv.w;
            acc[1][0] += a1*bv.x; acc[1][1] += a1*bv.y; acc[1][2] += a1*bv.z; acc[1][3] += a1*bv.w;
            acc[2][0] += a2*bv.x; acc[2][1] += a2*bv.y; acc[2][2] += a2*bv.z; acc[2][3] += a2*bv.w;
            acc[3][0] += a3*bv.x; acc[3][1] += a3*bv.y; acc[3][2] += a3*bv.z; acc[3][3] += a3*bv.w;
        }
        __syncthreads();
    }
    #pragma unroll
    for (int i = 0; i < 4; i++) {
        #pragma unroll
        for (int j = 0; j < 4; j++) {
            int n = n0 + tx*4 + j;
            g_xin[(r0 + ty*4 + i) * H_ + n] = acc[i][j] + b1[n];
        }
    }
}

// ================= Kernel 2: persistent recurrence =================
// h0 = tanh(xin[0]); for t=1..511: twice { h = tanh(xin[t] + h@Wh) }
// 128 CTAs: nt = bx>>3 (N-tile of 64 cols), ks = bx&7 (K-slice of 128).
// Wh slab (128x64, 32KB) SMEM-resident for all 1022 iterations.
// Deterministic: partials in fixed slots, fixed-order reduce (no atomics on data).
__global__ void recur_kernel(const float* __restrict__ w1, float* __restrict__ out_hist) {
    __shared__ __align__(16) float Whs[128*64];  // Whs[kk][nn], 32KB
    __shared__ __align__(16) float hs[64*32];    // hs[b][kk_sub], 8KB
    const int tid = threadIdx.x;
    const int bx  = blockIdx.x;
    const int nt = bx >> 3, ks = bx & 7;
    const int tx = tid & 15, ty = tid >> 4;

    // Load resident Wh slab: Wh[k][n] = w1[k*6144 + 1024 + n]
    for (int f = tid; f < 128*64; f += 256) {
        int kk = f >> 6, nn = f & 63;
        Whs[f] = w1[(ks*128 + kk) * SIXH + H_ + nt*64 + nn];
    }

    // Prologue: h0 = tanh(xin[0]); also out[:,0,:]
    #pragma unroll
    for (int i = 0; i < 2; i++) {
        int e = bx * 512 + i * 256 + tid;            // e in [0, 65536)
        float v = tanhf(g_xin[e]);
        g_h[e] = v;
        out_hist[(e >> 10) * (T_*H_) + (e & 1023)] = v;   // t = 0
    }
    grid_sync();

    for (int t = 1; t < T_; t++) {
        for (int j = 0; j < 2; j++) {
            // ---- GEMM phase: partial[ks][b][nt-cols] = h[:,ks-slice] @ Wh-slab ----
            float acc[4][4] = {};
            for (int kt = 0; kt < 4; kt++) {          // K sub-tiles of 32
                __syncthreads();
                // load hs[64][32] slice k = ks*128 + kt*32 + [0,32)
                #pragma unroll
                for (int i = 0; i < 2; i++) {
                    int f4 = tid + i * 256;           // 512 float4s
                    int b = f4 >> 3, q = f4 & 7;
                    float4 v = __ldcg((const float4*)&g_h[b * H_ + ks*128 + kt*32 + q*4]);
                    *(float4*)&hs[b * 32 + q * 4] = v;
                }
                __syncthreads();
                #pragma unroll 16
                for (int kk = 0; kk < 32; kk++) {
                    float a0 = hs[(ty*4+0)*32 + kk];
                    float a1 = hs[(ty*4+1)*32 + kk];
                    float a2 = hs[(ty*4+2)*32 + kk];
                    float a3 = hs[(ty*4+3)*32 + kk];
                    float4 bv = *(const float4*)&Whs[(kt*32 + kk)*64 + tx*4];
                    acc[0][0] += a0*bv.x; acc[0][1] += a0*bv.y; acc[0][2] += a0*bv.z; acc[0][3] += a0*bv.w;
                    acc[1][0] += a1*bv.x; acc[1][1] += a1*bv.y; acc[1][2] += a1*bv.z; acc[1][3] += a1*bv.w;
                    acc[2][0] += a2*bv.x; acc[2][1] += a2*bv.y; acc[2][2] += a2*bv.z; acc[2][3] += a2*bv.w;
                    acc[3][0] += a3*bv.x; acc[3][1] += a3*bv.y; acc[3][2] += a3*bv.z; acc[3][3] += a3*bv.w;
                }
            }
            #pragma unroll
            for (int i = 0; i < 4; i++) {
                #pragma unroll
                for (int jj = 0; jj < 4; jj++) {
                    g_part[ks * (B_*H_) + (ty*4 + i) * H_ + nt*64 + tx*4 + jj] = acc[i][jj];
                }
            }
            grid_sync();

            // ---- reduce + tanh phase ----
            const bool wr = (j == 1);
            #pragma unroll
            for (int i = 0; i < 2; i++) {
                int e = bx * 512 + i * 256 + tid;
                float s = g_xin[t * (B_*H_) + e];
                #pragma unroll
                for (int p = 0; p < 8; p++) s += __ldcg(&g_part[p * (B_*H_) + e]);
                float v = tanhf(s);
                g_h[e] = v;
                if (wr) out_hist[(e >> 10) * (T_*H_) + t * H_ + (e & 1023)] = v;
            }
            grid_sync();
        }
    }
}

// ================= Kernel 3: y = h_last @ fc_w^T + fc_b =================
// M=64, N=32000, K=1024. One 64x64 tile per CTA, 500 CTAs.
__global__ void fc_kernel(const float* __restrict__ fc_w, const float* __restrict__ fc_b,
                          float* __restrict__ y) {
    __shared__ __align__(16) float As[64*16];   // As[b][kk]
    __shared__ __align__(16) float Bs[16*64];   // Bs[kk][cc]
    const int tid = threadIdx.x;
    const int c0 = blockIdx.x * 64;
    const int tx = tid & 15, ty = tid >> 4;

    float acc[4][4] = {};
    for (int k0 = 0; k0 < H_; k0 += 16) {
        #pragma unroll
        for (int j = 0; j < 4; j++) {
            int f = tid + j * 256;
            int row = f >> 4, kk = f & 15;
            As[row * 16 + kk] = g_h[row * H_ + k0 + kk];
            Bs[kk * 64 + row] = fc_w[(c0 + row) * H_ + k0 + kk];  // transpose into Bs[kk][cc]
        }
        __syncthreads();
        #pragma unroll
        for (int kk = 0; kk < 16; kk++) {
            float a0 = As[(ty*4+0)*16 + kk];
            float a1 = As[(ty*4+1)*16 + kk];
            float a2 = As[(ty*4+2)*16 + kk];
            float a3 = As[(ty*4+3)*16 + kk];
            float4 bv = *(const float4*)&Bs[kk*64 + tx*4];
            acc[0][0] += a0*bv.x; acc[0][1] += a0*bv.y; acc[0][2] += a0*bv.z; acc[0][3] += a0*bv.w;
            acc[1][0] += a1*bv.x; acc[1][1] += a1*bv.y; acc[1][2] += a1*bv.z; acc[1][3] += a1*bv.w;
            acc[2][0] += a2*bv.x; acc[2][1] += a2*bv.y; acc[2][2] += a2*bv.z; acc[2][3] += a2*bv.w;
            acc[3][0] += a3*bv.x; acc[3][1] += a3*bv.y; acc[3][2] += a3*bv.z; acc[3][3] += a3*bv.w;
        }
        __syncthreads();
    }
    #pragma unroll
    for (int i = 0; i < 4; i++) {
        #pragma unroll
        for (int j = 0; j < 4; j++) {
            int c = c0 + tx*4 + j;
            y[(ty*4 + i) * C_ + c] = acc[i][j] + fc_b[c];
        }
    }
}

// ================= launch =================
extern "C" void kernel_launch(void* const* d_in, const int* in_sizes, int n_in,
                              void* d_out, int out_size) {
    const int*   x    = (const int*)  d_in[0];
    const float* emb  = (const float*)d_in[1];
    const float* w1   = (const float*)d_in[2];
    const float* b1   = (const float*)d_in[3];
    const float* fc_w = (const float*)d_in[4];
    const float* fc_b = (const float*)d_in[5];
    float* out = (float*)d_out;

    // 1) xin = emb[x] @ Wx + b   (writes g_xin)
    dim3 g1(H_/64, M_/64);
    xin_kernel<<<g1, 256>>>(x, emb, w1, b1);

    // 2) persistent recurrence: writes out history at out+YSIZE, final h in g_h
    recur_kernel<<<GRID_G, 256>>>(w1, out + YSIZE);

    // 3) y = h_last @ fc_w^T + fc_b  -> out[0 : B*C)
    fc_kernel<<<C_/64, 256>>>(fc_w, fc_b, out);
}